// round 2
// baseline (speedup 1.0000x reference)
#include <cuda_runtime.h>
#include <cstddef>

#define SEQ   512
#define BATCH 4096
#define INDIM 9
#define HID   64
#define OUTD  10
#define NTHREADS 128   // warps 0-1: layer1, warps 2-3: layer2

// Shared memory (floats):
//  hist : SEQ*HID   xw1[t] -> overwritten by h1[t] -> overwritten by h2[t]
//  xs   : SEQ*INDIM x[:, BATCH-1, :]
//  h1buf: 2*HID     layer1 double buffer
//  h2buf: 2*HID     layer2 double buffer
//  wfc  : OUTD*HID
//  bfc  : OUTD (+pad)
//  cnt  : 1 int  (layer1 progress)
#define SM_FLOATS (SEQ*HID + SEQ*INDIM + 2*HID + 2*HID + OUTD*HID + 16 + 16)
#define SM_BYTES  (SM_FLOATS * 4)

typedef unsigned long long ull;

__device__ __forceinline__ ull ffma2(ull a, ull b, ull c) {
    ull d; asm("fma.rn.f32x2 %0, %1, %2, %3;" : "=l"(d) : "l"(a), "l"(b), "l"(c));
    return d;
}
__device__ __forceinline__ ull fadd2(ull a, ull b) {
    ull d; asm("add.rn.f32x2 %0, %1, %2;" : "=l"(d) : "l"(a), "l"(b));
    return d;
}
__device__ __forceinline__ float f2sum(ull a) {
    float2 f = *reinterpret_cast<float2*>(&a);
    return f.x + f.y;
}
// tanh(x) = 1 - 2/(e^{2x}+1); exact saturation via inf/0, ~1e-7 accuracy
__device__ __forceinline__ float fast_tanh(float x) {
    float e, r;
    asm("ex2.approx.f32 %0, %1;" : "=f"(e) : "f"(x * 2.8853900817779268f));
    asm("rcp.approx.f32 %0, %1;" : "=f"(r) : "f"(e + 1.0f));
    return fmaf(-2.0f, r, 1.0f);
}
__device__ __forceinline__ void bar_sync(int id, int cnt_) {
    asm volatile("bar.sync %0, %1;" :: "r"(id), "r"(cnt_) : "memory");
}
__device__ __forceinline__ void st_release_s32(unsigned addr, int v) {
    asm volatile("st.release.cta.shared::cta.b32 [%0], %1;" :: "r"(addr), "r"(v) : "memory");
}
__device__ __forceinline__ int ld_acquire_s32(unsigned addr) {
    int v; asm volatile("ld.acquire.cta.shared::cta.b32 %0, [%1];" : "=r"(v) : "r"(addr) : "memory");
    return v;
}

__global__ __launch_bounds__(NTHREADS, 1)
void rnn_motion_kernel(const float* __restrict__ x,
                       const float* __restrict__ Wih0, const float* __restrict__ Whh0,
                       const float* __restrict__ bih0, const float* __restrict__ bhh0,
                       const float* __restrict__ Wih1, const float* __restrict__ Whh1,
                       const float* __restrict__ bih1, const float* __restrict__ bhh1,
                       const float* __restrict__ Wfc,  const float* __restrict__ bfc_g,
                       float* __restrict__ out)
{
    extern __shared__ float sm[];
    float* hist  = sm;                     // SEQ*HID
    float* xs    = hist + SEQ*HID;         // SEQ*INDIM
    float* h1buf = xs + SEQ*INDIM;         // 2*HID
    float* h2buf = h1buf + 2*HID;          // 2*HID
    float* wfc   = h2buf + 2*HID;          // OUTD*HID
    float* bfc   = wfc + OUTD*HID;         // OUTD (+pad)
    int*   cnt   = (int*)(bfc + 16);
    const unsigned cnt_addr = (unsigned)__cvta_generic_to_shared(cnt);

    const int tid = threadIdx.x;

    // -------- Prologue A: gather inputs, zero state --------
    for (int e = tid; e < SEQ*INDIM; e += NTHREADS) {
        int t = e / INDIM, k = e % INDIM;
        xs[e] = x[((size_t)t * BATCH + (BATCH - 1)) * INDIM + k];
    }
    for (int e = tid; e < OUTD*HID; e += NTHREADS) wfc[e] = Wfc[e];
    if (tid < OUTD) bfc[tid] = bfc_g[tid];
    for (int e = tid; e < 4*HID; e += NTHREADS) h1buf[e] = 0.0f;  // h1buf+h2buf
    if (tid == 0) *cnt = 0;
    __syncthreads();

    // -------- Prologue B: xw1[t][i] = x_t . Wih0[i] + (b_ih0+b_hh0)[i] --------
    {
        const int i = tid % HID;
        float wi[INDIM];
        #pragma unroll
        for (int k = 0; k < INDIM; ++k) wi[k] = Wih0[i*INDIM + k];
        const float bb = bih0[i] + bhh0[i];
        for (int t = tid / HID; t < SEQ; t += NTHREADS / HID) {
            float s = bb;
            #pragma unroll
            for (int k = 0; k < INDIM; ++k) s += xs[t*INDIM + k] * wi[k];
            hist[t*HID + i] = s;
        }
    }
    __syncthreads();

    // -------- Decoupled scan --------
    if (tid < HID) {
        // ===== layer1 producer: h1[t][i], publishes progress =====
        const int i = tid;
        ull wA[HID/2];
        {
            const ulonglong2* wp = reinterpret_cast<const ulonglong2*>(Whh0 + (size_t)i*HID);
            #pragma unroll
            for (int q = 0; q < HID/4; ++q) { ulonglong2 v = wp[q]; wA[2*q] = v.x; wA[2*q+1] = v.y; }
        }
        for (int t = 0; t < SEQ; ++t) {
            const int r = t & 1, w = r ^ 1;
            const float xw = hist[t*HID + i];
            ull a0=0, a1=0, a2=0, a3=0, a4=0, a5=0, a6=0, a7=0;
            const ulonglong2* hp = reinterpret_cast<const ulonglong2*>(h1buf + r*HID);
            #pragma unroll
            for (int q = 0; q < HID/4; q += 2) {
                ulonglong2 v0 = hp[q], v1 = hp[q+1];
                a0 = ffma2(v0.x, wA[2*q],   a0);
                a1 = ffma2(v0.y, wA[2*q+1], a1);
                a2 = ffma2(v1.x, wA[2*q+2], a2);
                a3 = ffma2(v1.y, wA[2*q+3], a3);
                // swap accumulator banks on alternate pairs for depth/2
                ull tmp;
                tmp = a0; a0 = a4; a4 = tmp;
                tmp = a1; a1 = a5; a5 = tmp;
                tmp = a2; a2 = a6; a6 = tmp;
                tmp = a3; a3 = a7; a7 = tmp;
            }
            ull s01 = fadd2(fadd2(a0, a4), fadd2(a1, a5));
            ull s23 = fadd2(fadd2(a2, a6), fadd2(a3, a7));
            float s  = xw + f2sum(fadd2(s01, s23));
            float hv = fast_tanh(s);
            h1buf[w*HID + i] = hv;
            hist[t*HID + i]  = hv;        // export h1[t]
            bar_sync(1, 64);              // drains STS among layer1 threads
            if (i == 0) st_release_s32(cnt_addr, t + 1);
        }
    } else {
        // ===== layer2 consumer: h2[t][i] =====
        const int i = tid - HID;
        ull wI[HID/2], wH[HID/2];
        {
            const ulonglong2* wp = reinterpret_cast<const ulonglong2*>(Wih1 + (size_t)i*HID);
            #pragma unroll
            for (int q = 0; q < HID/4; ++q) { ulonglong2 v = wp[q]; wI[2*q] = v.x; wI[2*q+1] = v.y; }
            const ulonglong2* wq = reinterpret_cast<const ulonglong2*>(Whh1 + (size_t)i*HID);
            #pragma unroll
            for (int q = 0; q < HID/4; ++q) { ulonglong2 v = wq[q]; wH[2*q] = v.x; wH[2*q+1] = v.y; }
        }
        const float bias2 = bih1[i] + bhh1[i];
        int avail = 0;
        float hv_prev = 0.0f;
        for (int t = 0; t < SEQ; ++t) {
            const int r = t & 1, w = r ^ 1;
            while (avail <= t) avail = ld_acquire_s32(cnt_addr);  // layer1 runs ahead; rarely spins
            // store h2[t-1] into its history slot (slot t-1 fully consumed last step)
            if (t > 0) hist[(t-1)*HID + i] = hv_prev;
            ull a0=0, a1=0, a2=0, a3=0, b0=0, b1=0, b2=0, b3=0;
            const ulonglong2* hp1 = reinterpret_cast<const ulonglong2*>(hist + t*HID);   // h1[t]
            const ulonglong2* hp2 = reinterpret_cast<const ulonglong2*>(h2buf + r*HID);  // h2[t-1]
            #pragma unroll
            for (int q = 0; q < HID/4; q += 2) {
                ulonglong2 u0 = hp1[q], u1 = hp1[q+1];
                ulonglong2 v0 = hp2[q], v1 = hp2[q+1];
                a0 = ffma2(u0.x, wI[2*q],   a0);
                a1 = ffma2(u0.y, wI[2*q+1], a1);
                a2 = ffma2(u1.x, wI[2*q+2], a2);
                a3 = ffma2(u1.y, wI[2*q+3], a3);
                b0 = ffma2(v0.x, wH[2*q],   b0);
                b1 = ffma2(v0.y, wH[2*q+1], b1);
                b2 = ffma2(v1.x, wH[2*q+2], b2);
                b3 = ffma2(v1.y, wH[2*q+3], b3);
            }
            ull sa = fadd2(fadd2(a0, a1), fadd2(a2, a3));
            ull sb = fadd2(fadd2(b0, b1), fadd2(b2, b3));
            float s  = bias2 + f2sum(fadd2(sa, sb));
            float hv = fast_tanh(s);
            h2buf[w*HID + i] = hv;
            hv_prev = hv;
            bar_sync(2, 64);
        }
        // final history slot
        hist[(SEQ-1)*HID + i] = hv_prev;
    }

    __syncthreads();

    // -------- Epilogue: out[t][o] = h2[t] . Wfc[o] + b_fc[o] --------
    for (int n = tid; n < SEQ*OUTD; n += NTHREADS) {
        const int t = n / OUTD, o = n % OUTD;
        const float4* h4 = reinterpret_cast<const float4*>(hist + t*HID);
        const float4* w4 = reinterpret_cast<const float4*>(wfc + o*HID);
        float s0 = bfc[o], s1 = 0.f, s2 = 0.f, s3 = 0.f;
        #pragma unroll
        for (int q = 0; q < HID/4; ++q) {
            float4 h = h4[q], w = w4[q];
            s0 = fmaf(h.x, w.x, s0);
            s1 = fmaf(h.y, w.y, s1);
            s2 = fmaf(h.z, w.z, s2);
            s3 = fmaf(h.w, w.w, s3);
        }
        out[n] = (s0 + s1) + (s2 + s3);
    }
}

extern "C" void kernel_launch(void* const* d_in, const int* in_sizes, int n_in,
                              void* d_out, int out_size) {
    (void)in_sizes; (void)n_in; (void)out_size;
    const float* x    = (const float*)d_in[0];
    const float* Wih0 = (const float*)d_in[1];
    const float* Whh0 = (const float*)d_in[2];
    const float* bih0 = (const float*)d_in[3];
    const float* bhh0 = (const float*)d_in[4];
    const float* Wih1 = (const float*)d_in[5];
    const float* Whh1 = (const float*)d_in[6];
    const float* bih1 = (const float*)d_in[7];
    const float* bhh1 = (const float*)d_in[8];
    const float* Wfc  = (const float*)d_in[9];
    const float* bfc  = (const float*)d_in[10];
    float* out = (float*)d_out;

    cudaFuncSetAttribute(rnn_motion_kernel,
                         cudaFuncAttributeMaxDynamicSharedMemorySize, SM_BYTES);
    rnn_motion_kernel<<<1, NTHREADS, SM_BYTES>>>(
        x, Wih0, Whh0, bih0, bhh0, Wih1, Whh1, bih1, bhh1, Wfc, bfc, out);
}